// round 14
// baseline (speedup 1.0000x reference)
#include <cuda_runtime.h>
#include <cuda_fp16.h>
#include <cstdint>

// ===================== problem constants =====================
constexpr int NTOK = 16384;     // 8*2048
constexpr int DDIM = 768;
constexpr int FDIM = 3072;
constexpr int NEXP = 8;
constexpr int CAP  = 2560;      // int(1.25*16384/8)
constexpr int MB   = CAP / 64;  // 40 m-tiles per expert
constexpr int FT   = FDIM / 128;
constexpr int NT   = DDIM / 128;

// ===================== device scratch (static; allocation-free) ==============
__device__ __half g_Xbuf[(size_t)NEXP * CAP * DDIM];   // [E][CAP][D] fp16
__device__ __half g_H   [(size_t)NEXP * CAP * FDIM];   // [E][CAP][F] fp16
__device__ __half g_w1t [(size_t)NEXP * FDIM * DDIM];  // [E][F][D] K-major fp16
__device__ __half g_w2t [(size_t)NEXP * DDIM * FDIM];  // [E][D][F] K-major fp16
__device__ int    g_route[NTOK];
__device__ float  g_prob [NTOK];
__device__ int    g_slot [NTOK];
__device__ int    g_tok  [NEXP * CAP];
__device__ int    g_cnt  [16];
__device__ int    g_ready[NTOK];        // router -> gather per-token flags
__device__ int    g_dep  [NEXP * MB];   // gemm1 -> gemm2 counters (target FT)

// ===================== PTX helpers (sm_80-era, compute_103-safe) =============
__device__ __forceinline__ uint32_t smem_u32(const void* p) {
    uint32_t a;
    asm("{ .reg .u64 t; cvta.to.shared.u64 t, %1; cvt.u32.u64 %0, t; }"
        : "=r"(a) : "l"(p));
    return a;
}

#define CP_ASYNC16(dst_smem, src_gmem) \
    asm volatile("cp.async.cg.shared.global [%0], [%1], 16;" \
        :: "r"(dst_smem), "l"(src_gmem))
#define CP_COMMIT() asm volatile("cp.async.commit_group;" ::: "memory")
#define CP_WAIT(n)  asm volatile("cp.async.wait_group %0;" :: "n"(n) : "memory")

__device__ __forceinline__ void ldsm_x4(uint32_t& r0, uint32_t& r1,
                                        uint32_t& r2, uint32_t& r3, uint32_t addr) {
    asm volatile("ldmatrix.sync.aligned.m8n8.x4.shared.b16 {%0,%1,%2,%3}, [%4];"
        : "=r"(r0), "=r"(r1), "=r"(r2), "=r"(r3) : "r"(addr));
}

__device__ __forceinline__ void mma16816(float* d, const uint32_t* a, const uint32_t* b) {
    asm volatile(
        "mma.sync.aligned.m16n8k16.row.col.f32.f16.f16.f32 "
        "{%0,%1,%2,%3}, {%4,%5,%6,%7}, {%8,%9}, {%0,%1,%2,%3};"
        : "+f"(d[0]), "+f"(d[1]), "+f"(d[2]), "+f"(d[3])
        : "r"(a[0]), "r"(a[1]), "r"(a[2]), "r"(a[3]), "r"(b[0]), "r"(b[1]));
}

__device__ __forceinline__ int ld_acquire(const int* p) {
    int v;
    asm volatile("ld.global.acquire.gpu.b32 %0, [%1];" : "=r"(v) : "l"(p) : "memory");
    return v;
}
__device__ __forceinline__ void st_release(int* p, int v) {
    asm volatile("st.global.release.gpu.b32 [%0], %1;" :: "l"(p), "r"(v) : "memory");
}
__device__ __forceinline__ void spin_until(const int* p, int target) {
    while (ld_acquire(p) < target) __nanosleep(128);
}

#define SMEM_SWIZZLE_128B(off) ((off) ^ (((off) >> 3) & 0x70))

// ===================== zero kernel =====================
__global__ void zero_kernel() {
    int i = blockIdx.x * blockDim.x + threadIdx.x;
    if (i < 16) g_cnt[i] = 0;
    if (i < NEXP * MB) g_dep[i] = 0;
    for (int j = i; j < NTOK; j += gridDim.x * blockDim.x) g_ready[j] = 0;
}

// ===================== prep kernel: router + transposes + gather ==============
// block layout (dispatch order matters):
//   [0, NRT)          router       (256 thr = 8 warps x 4 tokens)
//   [NRT, +NT1)       w1 transpose (256 thr, 64x32 tile)
//   [.., +NT2)        w2 transpose
//   [.., +NGA)        gather       (256 thr, 8 tokens, spins on per-token flag)
constexpr int NRT = NTOK / 32;                          // 512
constexpr int NT1 = (DDIM / 64) * (FDIM / 32) * NEXP;   // 9216
constexpr int NT2 = (FDIM / 64) * (DDIM / 32) * NEXP;   // 9216
constexpr int NGA = NTOK / 8;                           // 2048
constexpr int P_T1 = NRT;
constexpr int P_T2 = P_T1 + NT1;
constexpr int P_GA = P_T2 + NT2;
constexpr int PREP_BLOCKS = P_GA + NGA;

__device__ __forceinline__ void transpose_block64(const float* __restrict__ in,
                                                  __half* __restrict__ outp,
                                                  int R, int C, int e, int cx, int ry,
                                                  float tile[64][33]) {
    int c0 = cx * 32, r0 = ry * 64;
    const float* inp = in + (size_t)e * R * C;
    __half* op = outp + (size_t)e * R * C;
    int tx = threadIdx.x & 31, ty = threadIdx.x >> 5;   // ty 0..7
#pragma unroll
    for (int k = 0; k < 8; ++k)
        tile[ty + 8 * k][tx] = inp[(size_t)(r0 + ty + 8 * k) * C + c0 + tx];
    __syncthreads();
#pragma unroll
    for (int j = 0; j < 4; ++j) {
        int cl = ty + 8 * j;
        __half2 v = __floats2half2_rn(tile[2 * tx][cl], tile[2 * tx + 1][cl]);
        *(__half2*)(op + (size_t)(c0 + cl) * R + r0 + 2 * tx) = v;
    }
}

// router: 4 tokens per warp — 32 independent accumulator chains hide x-load
// latency; each coalesced switch_w float4-pair feeds 32 FMAs.
__device__ __forceinline__ void router_body(const float* __restrict__ x,
                                            const float* __restrict__ sw,
                                            const float* __restrict__ sb,
                                            int rb) {
    int w = rb * 8 + ((int)threadIdx.x >> 5);
    int lane = threadIdx.x & 31;
    int t0 = w * 4;
    const float* xp[4];
#pragma unroll
    for (int j = 0; j < 4; ++j) xp[j] = x + (size_t)(t0 + j) * DDIM;
    float a[4][8];
#pragma unroll
    for (int j = 0; j < 4; ++j)
#pragma unroll
        for (int e = 0; e < 8; e++) a[j][e] = 0.f;
    for (int d = lane; d < DDIM; d += 32) {
        float xv0 = xp[0][d], xv1 = xp[1][d], xv2 = xp[2][d], xv3 = xp[3][d];
        const float4* wr = (const float4*)(sw + (size_t)d * 8);
        float4 w0 = wr[0], w1 = wr[1];
        a[0][0] += xv0 * w0.x; a[0][1] += xv0 * w0.y;
        a[0][2] += xv0 * w0.z; a[0][3] += xv0 * w0.w;
        a[0][4] += xv0 * w1.x; a[0][5] += xv0 * w1.y;
        a[0][6] += xv0 * w1.z; a[0][7] += xv0 * w1.w;
        a[1][0] += xv1 * w0.x; a[1][1] += xv1 * w0.y;
        a[1][2] += xv1 * w0.z; a[1][3] += xv1 * w0.w;
        a[1][4] += xv1 * w1.x; a[1][5] += xv1 * w1.y;
        a[1][6] += xv1 * w1.z; a[1][7] += xv1 * w1.w;
        a[2][0] += xv2 * w0.x; a[2][1] += xv2 * w0.y;
        a[2][2] += xv2 * w0.z; a[2][3] += xv2 * w0.w;
        a[2][4] += xv2 * w1.x; a[2][5] += xv2 * w1.y;
        a[2][6] += xv2 * w1.z; a[2][7] += xv2 * w1.w;
        a[3][0] += xv3 * w0.x; a[3][1] += xv3 * w0.y;
        a[3][2] += xv3 * w0.z; a[3][3] += xv3 * w0.w;
        a[3][4] += xv3 * w1.x; a[3][5] += xv3 * w1.y;
        a[3][6] += xv3 * w1.z; a[3][7] += xv3 * w1.w;
    }
#pragma unroll
    for (int off = 16; off; off >>= 1) {
#pragma unroll
        for (int j = 0; j < 4; ++j)
#pragma unroll
            for (int e = 0; e < 8; e++)
                a[j][e] += __shfl_xor_sync(0xFFFFFFFFu, a[j][e], off);
    }
    if (lane == 0) {
#pragma unroll
        for (int j = 0; j < 4; ++j) {
            int t = t0 + j;
            float l[8];
            float best = -1e30f; int be = 0;
#pragma unroll
            for (int e = 0; e < 8; e++) {
                l[e] = a[j][e] + sb[e];
                if (l[e] > best) { best = l[e]; be = e; }
            }
            float s = 0.f;
#pragma unroll
            for (int e = 0; e < 8; e++) s += expf(l[e] - best);
            float p = 1.0f / s;
            g_route[t] = be;
            g_prob[t] = p;
            int slot = atomicAdd(&g_cnt[be], 1);
            g_slot[t] = slot;
            if (slot < CAP) g_tok[be * CAP + slot] = t;
            st_release(&g_ready[t], 1);
        }
    }
}

__global__ void __launch_bounds__(256) prep_kernel(const float* __restrict__ x,
                                                   const float* __restrict__ sw,
                                                   const float* __restrict__ sb,
                                                   const float* __restrict__ w1,
                                                   const float* __restrict__ w2,
                                                   float* __restrict__ out) {
    __shared__ float tile[64][33];
    int b = blockIdx.x;
    if (b < P_T1) {
        router_body(x, sw, sb, b);
    } else if (b < P_T2) {
        int bb = b - P_T1;
        int per_e = (DDIM / 64) * (FDIM / 32);
        int e = bb / per_e, rem = bb % per_e;
        int cx = rem % (FDIM / 32), ry = rem / (FDIM / 32);
        transpose_block64(w1, g_w1t, DDIM, FDIM, e, cx, ry, tile);
    } else if (b < P_GA) {
        int bb = b - P_T2;
        int per_e = (FDIM / 64) * (DDIM / 32);
        int e = bb / per_e, rem = bb % per_e;
        int cx = rem % (DDIM / 32), ry = rem / (DDIM / 32);
        transpose_block64(w2, g_w2t, FDIM, DDIM, e, cx, ry, tile);
    } else {
        // gather + passthrough, 1 warp per token (8 tokens per block)
        int w = threadIdx.x >> 5, lane = threadIdx.x & 31;
        int t = (b - P_GA) * 8 + w;
        if (lane == 0) spin_until(&g_ready[t], 1);
        __syncwarp();
        int e = g_route[t];
        int s = g_slot[t];
        const float4* src = (const float4*)(x + (size_t)t * DDIM);
        if (s < CAP) {
            __half2* dst = (__half2*)(g_Xbuf + ((size_t)e * CAP + s) * DDIM);
#pragma unroll
            for (int it = 0; it < 6; ++it) {
                int i = it * 32 + lane;
                float4 v = src[i];
                dst[i * 2]     = __floats2half2_rn(v.x, v.y);
                dst[i * 2 + 1] = __floats2half2_rn(v.z, v.w);
            }
        } else {
            float p = g_prob[t];
            float4* dst = (float4*)(out + (size_t)t * DDIM);
#pragma unroll
            for (int it = 0; it < 6; ++it) {
                int i = it * 32 + lane;
                float4 v = src[i];
                v.x *= p; v.y *= p; v.z *= p; v.w *= p;
                dst[i] = v;
            }
        }
    }
}

// ===================== GEMM core (measured-best R10/R11 structure) ===========
constexpr int SMEM_A_STAGE = 8192;
constexpr int SMEM_B_BASE  = 16384;
constexpr int SMEM_B_STAGE = 16384;
constexpr int SMEM_BYTES   = 49152;

__device__ __forceinline__ void issue_chunk(const __half* Ak, const __half* Bk,
                                            int ld, uint32_t sb, int buf, int tid) {
    uint32_t abase = sb + buf * SMEM_A_STAGE;
    uint32_t bbase = sb + SMEM_B_BASE + buf * SMEM_B_STAGE;
#pragma unroll
    for (int it = 0; it < 4; ++it) {
        int u = it * 128 + tid;
        int row = u >> 3, seg = u & 7;
        CP_ASYNC16(abase + SMEM_SWIZZLE_128B(row * 128 + seg * 16),
                   (const char*)(Ak + (size_t)row * ld) + seg * 16);
    }
#pragma unroll
    for (int it = 0; it < 8; ++it) {
        int u = it * 128 + tid;
        int row = u >> 3, seg = u & 7;
        CP_ASYNC16(bbase + SMEM_SWIZZLE_128B(row * 128 + seg * 16),
                   (const char*)(Bk + (size_t)row * ld) + seg * 16);
    }
}

__device__ __forceinline__ void compute_chunk(uint32_t abase, uint32_t bbase,
                                              int wm, int wn, int lane,
                                              float acc[2][8][4]) {
#pragma unroll
    for (int ks = 0; ks < 4; ++ks) {
        uint32_t af[2][4];
#pragma unroll
        for (int mt = 0; mt < 2; ++mt) {
            int row = wm * 32 + mt * 16 + (lane & 15);
            int colb = ks * 32 + (lane >> 4) * 16;
            ldsm_x4(af[mt][0], af[mt][1], af[mt][2], af[mt][3],
                    abase + SMEM_SWIZZLE_128B(row * 128 + colb));
        }
        uint32_t bf[8][2];
#pragma unroll
        for (int np = 0; np < 4; ++np) {
            int nrow = wn * 64 + np * 16 + (lane >> 4) * 8 + (lane & 7);
            int colb = ks * 32 + ((lane >> 3) & 1) * 16;
            uint32_t r0, r1, r2, r3;
            ldsm_x4(r0, r1, r2, r3, bbase + SMEM_SWIZZLE_128B(nrow * 128 + colb));
            bf[np * 2][0] = r0;     bf[np * 2][1] = r1;
            bf[np * 2 + 1][0] = r2; bf[np * 2 + 1][1] = r3;
        }
#pragma unroll
        for (int mt = 0; mt < 2; ++mt)
#pragma unroll
            for (int nt = 0; nt < 8; ++nt)
                mma16816(acc[mt][nt], af[mt], bf[nt]);
    }
}

__device__ __forceinline__ void gemm_mainloop(int nk, const __half* Ab, const __half* Bb,
                                              int ld, uint32_t sb, int tid,
                                              int wm, int wn, int lane,
                                              float acc[2][8][4]) {
    issue_chunk(Ab, Bb, ld, sb, 0, tid);
    CP_COMMIT();
    for (int kc = 0; kc < nk; ++kc) {
        if (kc + 1 < nk) {
            issue_chunk(Ab + (kc + 1) * 64, Bb + (kc + 1) * 64, ld, sb, (kc + 1) & 1, tid);
            CP_COMMIT();
            CP_WAIT(1);
        } else {
            CP_WAIT(0);
        }
        __syncthreads();
        compute_chunk(sb + (kc & 1) * SMEM_A_STAGE,
                      sb + SMEM_B_BASE + (kc & 1) * SMEM_B_STAGE,
                      wm, wn, lane, acc);
        __syncthreads();
    }
}

__device__ __forceinline__ float gelu_exact(float v) {
    return 0.5f * v * (1.0f + erff(v * 0.70710678118654752f));
}

// ===================== fused GEMM kernel (R11/R13, unchanged) ================
constexpr int NB1 = FT * MB * NEXP;   // 7680
constexpr int NB2 = NT * MB * NEXP;   // 1920

__global__ void __launch_bounds__(128, 4) moe_gemm_kernel(
    const float* __restrict__ b1, const float* __restrict__ b2,
    float* __restrict__ out)
{
    extern __shared__ char smem[];
    uint32_t sb = smem_u32(smem);
    int tid = threadIdx.x, lane = tid & 31, w = tid >> 5;
    int wm = w & 1, wn = w >> 1;
    int b = blockIdx.x;

    if (b < NB1) {
        // ---------------- GEMM1: H = gelu(Xbuf @ w1t^T + b1) ----------------
        int f = b % FT;
        int rest = b / FT;
        int mb = rest % MB;
        int e  = rest / MB;
        int m0 = mb * 64, f0 = f * 128;
        int cnt = g_cnt[e];
        int mcnt = cnt < CAP ? cnt : CAP;
        if (m0 >= mcnt) return;

        float acc[2][8][4];
#pragma unroll
        for (int a = 0; a < 2; a++)
#pragma unroll
            for (int q = 0; q < 8; q++)
#pragma unroll
                for (int c = 0; c < 4; c++) acc[a][q][c] = 0.f;

        const __half* Ab = g_Xbuf + ((size_t)e * CAP + m0) * DDIM;
        const __half* Bb = g_w1t + (size_t)e * FDIM * DDIM + (size_t)f0 * DDIM;
        gemm_mainloop(DDIM / 64, Ab, Bb, DDIM, sb, tid, wm, wn, lane, acc);

        const float* bb = b1 + (size_t)e * FDIM + f0 + wn * 64;
        __half* Hb = g_H + ((size_t)e * CAP + m0) * FDIM + f0;
        int lq = lane >> 2, lr = lane & 3;
#pragma unroll
        for (int nt = 0; nt < 8; ++nt) {
            float bc0 = bb[nt * 8 + lr * 2];
            float bc1 = bb[nt * 8 + lr * 2 + 1];
            int col = wn * 64 + nt * 8 + lr * 2;
#pragma unroll
            for (int mt = 0; mt < 2; ++mt) {
                int r0 = wm * 32 + mt * 16 + lq;
                __half2 v0 = __floats2half2_rn(gelu_exact(acc[mt][nt][0] + bc0),
                                               gelu_exact(acc[mt][nt][1] + bc1));
                __half2 v1 = __floats2half2_rn(gelu_exact(acc[mt][nt][2] + bc0),
                                               gelu_exact(acc[mt][nt][3] + bc1));
                *(__half2*)(Hb + (size_t)r0 * FDIM + col) = v0;
                *(__half2*)(Hb + (size_t)(r0 + 8) * FDIM + col) = v1;
            }
        }
        __threadfence();
        __syncthreads();
        if (tid == 0) atomicAdd(&g_dep[e * MB + mb], 1);
    } else {
        // ---------------- GEMM2: out = (H @ w2t^T + b2) * prob --------------
        int b2i = b - NB1;
        int n = b2i % NT;
        int rest = b2i / NT;
        int mb = rest % MB;
        int e  = rest / MB;
        int m0 = mb * 64, n0 = n * 128;
        int cnt = g_cnt[e];
        int mcnt = cnt < CAP ? cnt : CAP;
        if (m0 >= mcnt) return;

        if (tid == 0) spin_until(&g_dep[e * MB + mb], FT);
        __syncthreads();

        float acc[2][8][4];
#pragma unroll
        for (int a = 0; a < 2; a++)
#pragma unroll
            for (int q = 0; q < 8; q++)
#pragma unroll
                for (int c = 0; c < 4; c++) acc[a][q][c] = 0.f;

        const __half* Ab = g_H + ((size_t)e * CAP + m0) * FDIM;
        const __half* Bb = g_w2t + (size_t)e * DDIM * FDIM + (size_t)n0 * FDIM;
        gemm_mainloop(FDIM / 64, Ab, Bb, FDIM, sb, tid, wm, wn, lane, acc);

        const float* bb = b2 + (size_t)e * DDIM + n0 + wn * 64;
        int lq = lane >> 2, lr = lane & 3;
        float bc0[8], bc1[8];
#pragma unroll
        for (int nt = 0; nt < 8; ++nt) {
            bc0[nt] = bb[nt * 8 + lr * 2];
            bc1[nt] = bb[nt * 8 + lr * 2 + 1];
        }
#pragma unroll
        for (int mt = 0; mt < 2; ++mt) {
#pragma unroll
            for (int half = 0; half < 2; ++half) {
                int row = wm * 32 + mt * 16 + lq + half * 8;
                int gm = m0 + row;
                if (gm < mcnt) {
                    int tok = g_tok[e * CAP + gm];
                    float p = g_prob[tok];
                    float* orow = out + (size_t)tok * DDIM + n0 + wn * 64;
#pragma unroll
                    for (int nt = 0; nt < 8; ++nt) {
                        float2 v;
                        v.x = (acc[mt][nt][half * 2]     + bc0[nt]) * p;
                        v.y = (acc[mt][nt][half * 2 + 1] + bc1[nt]) * p;
                        *(float2*)(orow + nt * 8 + lr * 2) = v;
                    }
                }
            }
        }
    }
}

// ===================== launch =====================
extern "C" void kernel_launch(void* const* d_in, const int* in_sizes, int n_in,
                              void* d_out, int out_size) {
    const float* x   = (const float*)d_in[0];
    const float* sw  = (const float*)d_in[1];
    const float* sbv = (const float*)d_in[2];
    const float* w1  = (const float*)d_in[3];
    const float* b1  = (const float*)d_in[4];
    const float* w2  = (const float*)d_in[5];
    const float* b2  = (const float*)d_in[6];
    float* out = (float*)d_out;

    cudaFuncSetAttribute(moe_gemm_kernel, cudaFuncAttributeMaxDynamicSharedMemorySize, SMEM_BYTES);

    zero_kernel<<<32, 256>>>();
    prep_kernel<<<PREP_BLOCKS, 256>>>(x, sw, sbv, w1, w2, out);
    moe_gemm_kernel<<<NB1 + NB2, 128, SMEM_BYTES>>>(b1, b2, out);
}

// round 15
// speedup vs baseline: 1.0350x; 1.0350x over previous
#include <cuda_runtime.h>
#include <cuda_fp16.h>
#include <cstdint>

// ===================== problem constants =====================
constexpr int NTOK = 16384;     // 8*2048
constexpr int DDIM = 768;
constexpr int FDIM = 3072;
constexpr int NEXP = 8;
constexpr int CAP  = 2560;      // int(1.25*16384/8)
constexpr int MB   = CAP / 64;  // 40 m-tiles per expert
constexpr int FT   = FDIM / 128;
constexpr int NT   = DDIM / 128;

// ===================== device scratch (static; allocation-free) ==============
__device__ __half g_Xbuf[(size_t)NEXP * CAP * DDIM];   // [E][CAP][D] fp16
__device__ __half g_H   [(size_t)NEXP * CAP * FDIM];   // [E][CAP][F] fp16
__device__ __half g_w1t [(size_t)NEXP * FDIM * DDIM];  // [E][F][D] K-major fp16
__device__ __half g_w2t [(size_t)NEXP * DDIM * FDIM];  // [E][D][F] K-major fp16
__device__ float  g_prob [NTOK];
__device__ int    g_tok  [NEXP * CAP];
__device__ int    g_cnt  [16];
__device__ int    g_dep  [NEXP * MB];   // gemm1 -> gemm2 counters (target FT)

// ===================== PTX helpers (sm_80-era, compute_103-safe) =============
__device__ __forceinline__ uint32_t smem_u32(const void* p) {
    uint32_t a;
    asm("{ .reg .u64 t; cvta.to.shared.u64 t, %1; cvt.u32.u64 %0, t; }"
        : "=r"(a) : "l"(p));
    return a;
}

#define CP_ASYNC16(dst_smem, src_gmem) \
    asm volatile("cp.async.cg.shared.global [%0], [%1], 16;" \
        :: "r"(dst_smem), "l"(src_gmem))
#define CP_COMMIT() asm volatile("cp.async.commit_group;" ::: "memory")
#define CP_WAIT(n)  asm volatile("cp.async.wait_group %0;" :: "n"(n) : "memory")

__device__ __forceinline__ void ldsm_x4(uint32_t& r0, uint32_t& r1,
                                        uint32_t& r2, uint32_t& r3, uint32_t addr) {
    asm volatile("ldmatrix.sync.aligned.m8n8.x4.shared.b16 {%0,%1,%2,%3}, [%4];"
        : "=r"(r0), "=r"(r1), "=r"(r2), "=r"(r3) : "r"(addr));
}

__device__ __forceinline__ void mma16816(float* d, const uint32_t* a, const uint32_t* b) {
    asm volatile(
        "mma.sync.aligned.m16n8k16.row.col.f32.f16.f16.f32 "
        "{%0,%1,%2,%3}, {%4,%5,%6,%7}, {%8,%9}, {%0,%1,%2,%3};"
        : "+f"(d[0]), "+f"(d[1]), "+f"(d[2]), "+f"(d[3])
        : "r"(a[0]), "r"(a[1]), "r"(a[2]), "r"(a[3]), "r"(b[0]), "r"(b[1]));
}

__device__ __forceinline__ int ld_acquire(const int* p) {
    int v;
    asm volatile("ld.global.acquire.gpu.b32 %0, [%1];" : "=r"(v) : "l"(p) : "memory");
    return v;
}
__device__ __forceinline__ void spin_until(const int* p, int target) {
    while (ld_acquire(p) < target) __nanosleep(128);
}

#define SMEM_SWIZZLE_128B(off) ((off) ^ (((off) >> 3) & 0x70))

// ===================== zero kernel =====================
__global__ void zero_kernel() {
    int i = threadIdx.x;
    if (i < 16) g_cnt[i] = 0;
    for (int j = i; j < NEXP * MB; j += blockDim.x) g_dep[j] = 0;
}

// ===================== prep kernel: router+gather fused, + transposes ========
// block layout:
//   [0, NRG)        router+gather (256 thr = 8 warps, 1 token per warp)
//   [NRG, +NT1)     w1 transpose  (256 thr, 64x32 tile)
//   [.., +NT2)      w2 transpose
// No inter-block dependencies inside prep.
constexpr int NRG = NTOK / 8;                           // 2048
constexpr int NT1 = (DDIM / 64) * (FDIM / 32) * NEXP;   // 9216
constexpr int NT2 = (FDIM / 64) * (DDIM / 32) * NEXP;   // 9216
constexpr int P_T1 = NRG;
constexpr int P_T2 = P_T1 + NT1;
constexpr int PREP_BLOCKS = P_T2 + NT2;

__device__ __forceinline__ void transpose_block64(const float* __restrict__ in,
                                                  __half* __restrict__ outp,
                                                  int R, int C, int e, int cx, int ry,
                                                  float tile[64][33]) {
    int c0 = cx * 32, r0 = ry * 64;
    const float* inp = in + (size_t)e * R * C;
    __half* op = outp + (size_t)e * R * C;
    int tx = threadIdx.x & 31, ty = threadIdx.x >> 5;   // ty 0..7
#pragma unroll
    for (int k = 0; k < 8; ++k)
        tile[ty + 8 * k][tx] = inp[(size_t)(r0 + ty + 8 * k) * C + c0 + tx];
    __syncthreads();
#pragma unroll
    for (int j = 0; j < 4; ++j) {
        int cl = ty + 8 * j;
        __half2 v = __floats2half2_rn(tile[2 * tx][cl], tile[2 * tx + 1][cl]);
        *(__half2*)(op + (size_t)(c0 + cl) * R + r0 + 2 * tx) = v;
    }
}

// router + gather fused: one warp per token. Logits from a first pass over the
// row (fills L1); route decided by lane 0 and broadcast; the same warp then
// re-reads the (L1-hot) row as float4 and writes fp16 into the expert buffer.
__device__ __forceinline__ void route_gather_body(const float* __restrict__ x,
                                                  const float* __restrict__ sw,
                                                  const float* __restrict__ sb,
                                                  float* __restrict__ out,
                                                  int rb) {
    int w = (int)threadIdx.x >> 5;
    int lane = threadIdx.x & 31;
    int t = rb * 8 + w;
    const float* xr = x + (size_t)t * DDIM;

    float a[8];
#pragma unroll
    for (int e = 0; e < 8; e++) a[e] = 0.f;
#pragma unroll 4
    for (int d = lane; d < DDIM; d += 32) {
        float xv = xr[d];
        const float4* wr = (const float4*)(sw + (size_t)d * 8);
        float4 w0 = wr[0], w1 = wr[1];
        a[0] += xv * w0.x; a[1] += xv * w0.y;
        a[2] += xv * w0.z; a[3] += xv * w0.w;
        a[4] += xv * w1.x; a[5] += xv * w1.y;
        a[6] += xv * w1.z; a[7] += xv * w1.w;
    }
#pragma unroll
    for (int off = 16; off; off >>= 1)
#pragma unroll
        for (int e = 0; e < 8; e++)
            a[e] += __shfl_xor_sync(0xFFFFFFFFu, a[e], off);

    int be = 0, slot = 0;
    float p = 0.f;
    if (lane == 0) {
        float l[8];
        float best = -1e30f;
#pragma unroll
        for (int e = 0; e < 8; e++) {
            l[e] = a[e] + sb[e];
            if (l[e] > best) { best = l[e]; be = e; }
        }
        float s = 0.f;
#pragma unroll
        for (int e = 0; e < 8; e++) s += expf(l[e] - best);
        p = 1.0f / s;
        g_prob[t] = p;
        slot = atomicAdd(&g_cnt[be], 1);
        if (slot < CAP) g_tok[be * CAP + slot] = t;
    }
    be   = __shfl_sync(0xFFFFFFFFu, be, 0);
    slot = __shfl_sync(0xFFFFFFFFu, slot, 0);
    p    = __shfl_sync(0xFFFFFFFFu, p, 0);

    const float4* src = (const float4*)xr;
    if (slot < CAP) {
        __half2* dst = (__half2*)(g_Xbuf + ((size_t)be * CAP + slot) * DDIM);
#pragma unroll
        for (int it = 0; it < 6; ++it) {
            int i = it * 32 + lane;
            float4 v = src[i];
            dst[i * 2]     = __floats2half2_rn(v.x, v.y);
            dst[i * 2 + 1] = __floats2half2_rn(v.z, v.w);
        }
    } else {
        float4* dst = (float4*)(out + (size_t)t * DDIM);
#pragma unroll
        for (int it = 0; it < 6; ++it) {
            int i = it * 32 + lane;
            float4 v = src[i];
            v.x *= p; v.y *= p; v.z *= p; v.w *= p;
            dst[i] = v;
        }
    }
}

__global__ void __launch_bounds__(256) prep_kernel(const float* __restrict__ x,
                                                   const float* __restrict__ sw,
                                                   const float* __restrict__ sb,
                                                   const float* __restrict__ w1,
                                                   const float* __restrict__ w2,
                                                   float* __restrict__ out) {
    __shared__ float tile[64][33];
    int b = blockIdx.x;
    if (b < P_T1) {
        route_gather_body(x, sw, sb, out, b);
    } else if (b < P_T2) {
        int bb = b - P_T1;
        int per_e = (DDIM / 64) * (FDIM / 32);
        int e = bb / per_e, rem = bb % per_e;
        int cx = rem % (FDIM / 32), ry = rem / (FDIM / 32);
        transpose_block64(w1, g_w1t, DDIM, FDIM, e, cx, ry, tile);
    } else {
        int bb = b - P_T2;
        int per_e = (FDIM / 64) * (DDIM / 32);
        int e = bb / per_e, rem = bb % per_e;
        int cx = rem % (DDIM / 32), ry = rem / (DDIM / 32);
        transpose_block64(w2, g_w2t, FDIM, DDIM, e, cx, ry, tile);
    }
}

// ===================== GEMM core (measured-best R10/R11 structure) ===========
constexpr int SMEM_A_STAGE = 8192;
constexpr int SMEM_B_BASE  = 16384;
constexpr int SMEM_B_STAGE = 16384;
constexpr int SMEM_BYTES   = 49152;

__device__ __forceinline__ void issue_chunk(const __half* Ak, const __half* Bk,
                                            int ld, uint32_t sb, int buf, int tid) {
    uint32_t abase = sb + buf * SMEM_A_STAGE;
    uint32_t bbase = sb + SMEM_B_BASE + buf * SMEM_B_STAGE;
#pragma unroll
    for (int it = 0; it < 4; ++it) {
        int u = it * 128 + tid;
        int row = u >> 3, seg = u & 7;
        CP_ASYNC16(abase + SMEM_SWIZZLE_128B(row * 128 + seg * 16),
                   (const char*)(Ak + (size_t)row * ld) + seg * 16);
    }
#pragma unroll
    for (int it = 0; it < 8; ++it) {
        int u = it * 128 + tid;
        int row = u >> 3, seg = u & 7;
        CP_ASYNC16(bbase + SMEM_SWIZZLE_128B(row * 128 + seg * 16),
                   (const char*)(Bk + (size_t)row * ld) + seg * 16);
    }
}

__device__ __forceinline__ void compute_chunk(uint32_t abase, uint32_t bbase,
                                              int wm, int wn, int lane,
                                              float acc[2][8][4]) {
#pragma unroll
    for (int ks = 0; ks < 4; ++ks) {
        uint32_t af[2][4];
#pragma unroll
        for (int mt = 0; mt < 2; ++mt) {
            int row = wm * 32 + mt * 16 + (lane & 15);
            int colb = ks * 32 + (lane >> 4) * 16;
            ldsm_x4(af[mt][0], af[mt][1], af[mt][2], af[mt][3],
                    abase + SMEM_SWIZZLE_128B(row * 128 + colb));
        }
        uint32_t bf[8][2];
#pragma unroll
        for (int np = 0; np < 4; ++np) {
            int nrow = wn * 64 + np * 16 + (lane >> 4) * 8 + (lane & 7);
            int colb = ks * 32 + ((lane >> 3) & 1) * 16;
            uint32_t r0, r1, r2, r3;
            ldsm_x4(r0, r1, r2, r3, bbase + SMEM_SWIZZLE_128B(nrow * 128 + colb));
            bf[np * 2][0] = r0;     bf[np * 2][1] = r1;
            bf[np * 2 + 1][0] = r2; bf[np * 2 + 1][1] = r3;
        }
#pragma unroll
        for (int mt = 0; mt < 2; ++mt)
#pragma unroll
            for (int nt = 0; nt < 8; ++nt)
                mma16816(acc[mt][nt], af[mt], bf[nt]);
    }
}

__device__ __forceinline__ void gemm_mainloop(int nk, const __half* Ab, const __half* Bb,
                                              int ld, uint32_t sb, int tid,
                                              int wm, int wn, int lane,
                                              float acc[2][8][4]) {
    issue_chunk(Ab, Bb, ld, sb, 0, tid);
    CP_COMMIT();
    for (int kc = 0; kc < nk; ++kc) {
        if (kc + 1 < nk) {
            issue_chunk(Ab + (kc + 1) * 64, Bb + (kc + 1) * 64, ld, sb, (kc + 1) & 1, tid);
            CP_COMMIT();
            CP_WAIT(1);
        } else {
            CP_WAIT(0);
        }
        __syncthreads();
        compute_chunk(sb + (kc & 1) * SMEM_A_STAGE,
                      sb + SMEM_B_BASE + (kc & 1) * SMEM_B_STAGE,
                      wm, wn, lane, acc);
        __syncthreads();
    }
}

__device__ __forceinline__ float gelu_exact(float v) {
    return 0.5f * v * (1.0f + erff(v * 0.70710678118654752f));
}

// ===================== fused GEMM kernel (R11/R13, unchanged) ================
constexpr int NB1 = FT * MB * NEXP;   // 7680
constexpr int NB2 = NT * MB * NEXP;   // 1920

__global__ void __launch_bounds__(128, 4) moe_gemm_kernel(
    const float* __restrict__ b1, const float* __restrict__ b2,
    float* __restrict__ out)
{
    extern __shared__ char smem[];
    uint32_t sb = smem_u32(smem);
    int tid = threadIdx.x, lane = tid & 31, w = tid >> 5;
    int wm = w & 1, wn = w >> 1;
    int b = blockIdx.x;

    if (b < NB1) {
        // ---------------- GEMM1: H = gelu(Xbuf @ w1t^T + b1) ----------------
        int f = b % FT;
        int rest = b / FT;
        int mb = rest % MB;
        int e  = rest / MB;
        int m0 = mb * 64, f0 = f * 128;
        int cnt = g_cnt[e];
        int mcnt = cnt < CAP ? cnt : CAP;
        if (m0 >= mcnt) return;

        float acc[2][8][4];
#pragma unroll
        for (int a = 0; a < 2; a++)
#pragma unroll
            for (int q = 0; q < 8; q++)
#pragma unroll
                for (int c = 0; c < 4; c++) acc[a][q][c] = 0.f;

        const __half* Ab = g_Xbuf + ((size_t)e * CAP + m0) * DDIM;
        const __half* Bb = g_w1t + (size_t)e * FDIM * DDIM + (size_t)f0 * DDIM;
        gemm_mainloop(DDIM / 64, Ab, Bb, DDIM, sb, tid, wm, wn, lane, acc);

        const float* bb = b1 + (size_t)e * FDIM + f0 + wn * 64;
        __half* Hb = g_H + ((size_t)e * CAP + m0) * FDIM + f0;
        int lq = lane >> 2, lr = lane & 3;
#pragma unroll
        for (int nt = 0; nt < 8; ++nt) {
            float bc0 = bb[nt * 8 + lr * 2];
            float bc1 = bb[nt * 8 + lr * 2 + 1];
            int col = wn * 64 + nt * 8 + lr * 2;
#pragma unroll
            for (int mt = 0; mt < 2; ++mt) {
                int r0 = wm * 32 + mt * 16 + lq;
                __half2 v0 = __floats2half2_rn(gelu_exact(acc[mt][nt][0] + bc0),
                                               gelu_exact(acc[mt][nt][1] + bc1));
                __half2 v1 = __floats2half2_rn(gelu_exact(acc[mt][nt][2] + bc0),
                                               gelu_exact(acc[mt][nt][3] + bc1));
                *(__half2*)(Hb + (size_t)r0 * FDIM + col) = v0;
                *(__half2*)(Hb + (size_t)(r0 + 8) * FDIM + col) = v1;
            }
        }
        __threadfence();
        __syncthreads();
        if (tid == 0) atomicAdd(&g_dep[e * MB + mb], 1);
    } else {
        // ---------------- GEMM2: out = (H @ w2t^T + b2) * prob --------------
        int b2i = b - NB1;
        int n = b2i % NT;
        int rest = b2i / NT;
        int mb = rest % MB;
        int e  = rest / MB;
        int m0 = mb * 64, n0 = n * 128;
        int cnt = g_cnt[e];
        int mcnt = cnt < CAP ? cnt : CAP;
        if (m0 >= mcnt) return;

        if (tid == 0) spin_until(&g_dep[e * MB + mb], FT);
        __syncthreads();

        float acc[2][8][4];
#pragma unroll
        for (int a = 0; a < 2; a++)
#pragma unroll
            for (int q = 0; q < 8; q++)
#pragma unroll
                for (int c = 0; c < 4; c++) acc[a][q][c] = 0.f;

        const __half* Ab = g_H + ((size_t)e * CAP + m0) * FDIM;
        const __half* Bb = g_w2t + (size_t)e * DDIM * FDIM + (size_t)n0 * FDIM;
        gemm_mainloop(FDIM / 64, Ab, Bb, FDIM, sb, tid, wm, wn, lane, acc);

        const float* bb = b2 + (size_t)e * DDIM + n0 + wn * 64;
        int lq = lane >> 2, lr = lane & 3;
        float bc0[8], bc1[8];
#pragma unroll
        for (int nt = 0; nt < 8; ++nt) {
            bc0[nt] = bb[nt * 8 + lr * 2];
            bc1[nt] = bb[nt * 8 + lr * 2 + 1];
        }
#pragma unroll
        for (int mt = 0; mt < 2; ++mt) {
#pragma unroll
            for (int half = 0; half < 2; ++half) {
                int row = wm * 32 + mt * 16 + lq + half * 8;
                int gm = m0 + row;
                if (gm < mcnt) {
                    int tok = g_tok[e * CAP + gm];
                    float p = g_prob[tok];
                    float* orow = out + (size_t)tok * DDIM + n0 + wn * 64;
#pragma unroll
                    for (int nt = 0; nt < 8; ++nt) {
                        float2 v;
                        v.x = (acc[mt][nt][half * 2]     + bc0[nt]) * p;
                        v.y = (acc[mt][nt][half * 2 + 1] + bc1[nt]) * p;
                        *(float2*)(orow + nt * 8 + lr * 2) = v;
                    }
                }
            }
        }
    }
}

// ===================== launch =====================
extern "C" void kernel_launch(void* const* d_in, const int* in_sizes, int n_in,
                              void* d_out, int out_size) {
    const float* x   = (const float*)d_in[0];
    const float* sw  = (const float*)d_in[1];
    const float* sbv = (const float*)d_in[2];
    const float* w1  = (const float*)d_in[3];
    const float* b1  = (const float*)d_in[4];
    const float* w2  = (const float*)d_in[5];
    const float* b2  = (const float*)d_in[6];
    float* out = (float*)d_out;

    cudaFuncSetAttribute(moe_gemm_kernel, cudaFuncAttributeMaxDynamicSharedMemorySize, SMEM_BYTES);

    zero_kernel<<<1, 256>>>();
    prep_kernel<<<PREP_BLOCKS, 256>>>(x, sw, sbv, w1, w2, out);
    moe_gemm_kernel<<<NB1 + NB2, 128, SMEM_BYTES>>>(b1, b2, out);
}